// round 13
// baseline (speedup 1.0000x reference)
#include <cuda_runtime.h>
#include <cuda_bf16.h>
#include <cstdint>

#define B_   16
#define C_   512
#define NH   8
#define HD   64
#define N_   1024
#define G_   32
#define CPG  16
#define EPSV 1e-5f
#define LOG2E 1.4426950408889634f

// ---------------- scratch (device globals; no allocation allowed) -----------
__device__ __nv_bfloat16 g_qext[(size_t)B_ * NH * N_ * 128];   // [b][h][n][hi64|lo64], pre-scaled
__device__ __nv_bfloat16 g_kext[(size_t)B_ * NH * N_ * 128];   // [b][h][n][hi64|lo64]
__device__ __nv_bfloat16 g_vhi[(size_t)B_ * NH * HD * N_];     // [b][h][d][n]
__device__ __nv_bfloat16 g_vlo[(size_t)B_ * NH * HD * N_];
__device__ __nv_bfloat16 g_hn[(size_t)B_ * N_ * 1024];         // [b][n][hi512|lo512]
__device__ __nv_bfloat16 g_obuf[(size_t)B_ * N_ * 1024];       // [b][n][hi512|lo512]
__device__ __nv_bfloat16 g_wqkv[(size_t)(3*C_) * 1024];        // [o][hi512|lo512]
__device__ __nv_bfloat16 g_wproj[(size_t)C_ * 1024];           // [o][hi512|lo512]

// ---------------- PTX helpers (baseline-safe for compute_103) ---------------
__device__ __forceinline__ uint32_t smem_u32(const void* p) {
    uint32_t a;
    asm("{ .reg .u64 t; cvta.to.shared.u64 t, %1; cvt.u32.u64 %0, t; }" : "=r"(a) : "l"(p));
    return a;
}
__device__ __forceinline__ void ldsm_x4(uint32_t* r, uint32_t addr) {
    asm volatile("ldmatrix.sync.aligned.m8n8.x4.shared.b16 {%0,%1,%2,%3}, [%4];"
                 : "=r"(r[0]), "=r"(r[1]), "=r"(r[2]), "=r"(r[3]) : "r"(addr));
}
__device__ __forceinline__ void mma_bf16(float* c, const uint32_t* a, const uint32_t* b) {
    asm volatile("mma.sync.aligned.m16n8k16.row.col.f32.bf16.bf16.f32 "
                 "{%0,%1,%2,%3}, {%4,%5,%6,%7}, {%8,%9}, {%0,%1,%2,%3};"
                 : "+f"(c[0]), "+f"(c[1]), "+f"(c[2]), "+f"(c[3])
                 : "r"(a[0]), "r"(a[1]), "r"(a[2]), "r"(a[3]), "r"(b[0]), "r"(b[1]));
}
__device__ __forceinline__ float ex2(float x) {
    float r; asm("ex2.approx.f32 %0, %1;" : "=f"(r) : "f"(x)); return r;
}
__device__ __forceinline__ uint32_t packbf2(float a, float b) {
    __nv_bfloat162 t; t.x = __float2bfloat16(a); t.y = __float2bfloat16(b);
    return *(uint32_t*)&t;
}
#define CPA(dst, src) \
    asm volatile("cp.async.cg.shared.global [%0], [%1], 16;" :: "r"(dst), "l"(src))
#define CPCOMMIT() asm volatile("cp.async.commit_group;")
#define CPWAIT(n)  asm volatile("cp.async.wait_group %0;" :: "n"(n))

// ---------------------------------------------------------------------------
// 0) Weight split: w[o][c] fp32 -> 2-plane [o][hi512|lo512]
// ---------------------------------------------------------------------------
__global__ void convw_kernel(const float* __restrict__ wq, const float* __restrict__ wp) {
    int r = blockIdx.x;
    const float* src = (r < 3*C_) ? wq + (size_t)r * C_ : wp + (size_t)(r - 3*C_) * C_;
    __nv_bfloat16* dst = (r < 3*C_) ? g_wqkv + (size_t)r * 1024
                                    : g_wproj + (size_t)(r - 3*C_) * 1024;
    for (int c = threadIdx.x; c < C_; c += 128) {
        float v = src[c];
        __nv_bfloat16 hi = __float2bfloat16(v);
        dst[c]       = hi;
        dst[512 + c] = __float2bfloat16(v - __bfloat162float(hi));
    }
}

// ---------------------------------------------------------------------------
// 1) GroupNorm + transpose + bf16 split -> g_hn [b][n][hi512|lo512]
// ---------------------------------------------------------------------------
__global__ __launch_bounds__(256) void gn_kernel(const float* __restrict__ x,
                                                 const float* __restrict__ w,
                                                 const float* __restrict__ bb) {
    int bg = blockIdx.x;
    int g = bg & (G_ - 1), b = bg >> 5;
    const float4* x4 = (const float4*)(x + (size_t)bg * CPG * N_);
    int tid = threadIdx.x;

    float s = 0.f, s2 = 0.f;
    #pragma unroll
    for (int i = 0; i < 16; i++) {
        float4 v = x4[tid + i * 256];
        s  += v.x + v.y + v.z + v.w;
        s2 += v.x*v.x + v.y*v.y + v.z*v.z + v.w*v.w;
    }
    __shared__ float rs[256], rs2[256];
    rs[tid] = s; rs2[tid] = s2;
    __syncthreads();
    for (int off = 128; off > 0; off >>= 1) {
        if (tid < off) { rs[tid] += rs[tid+off]; rs2[tid] += rs2[tid+off]; }
        __syncthreads();
    }
    float mean = rs[0] * (1.f/16384.f);
    float var  = rs2[0] * (1.f/16384.f) - mean*mean;
    float rstd = rsqrtf(var + EPSV);

    float sc[CPG], sh[CPG];
    #pragma unroll
    for (int c16 = 0; c16 < CPG; c16++) {
        int c = g*CPG + c16;
        sc[c16] = rstd * w[c];
        sh[c16] = bb[c] - mean * sc[c16];
    }

    float4 vals[CPG];
    #pragma unroll
    for (int c16 = 0; c16 < CPG; c16++) {
        float4 v = x4[c16 * 256 + tid];
        vals[c16].x = v.x*sc[c16]+sh[c16]; vals[c16].y = v.y*sc[c16]+sh[c16];
        vals[c16].z = v.z*sc[c16]+sh[c16]; vals[c16].w = v.w*sc[c16]+sh[c16];
    }
    union Pack { __nv_bfloat16 h[CPG]; uint4 v[2]; };
    #pragma unroll
    for (int j = 0; j < 4; j++) {
        Pack hiP, loP;
        #pragma unroll
        for (int c16 = 0; c16 < CPG; c16++) {
            float v = j == 0 ? vals[c16].x : j == 1 ? vals[c16].y
                    : j == 2 ? vals[c16].z : vals[c16].w;
            __nv_bfloat16 hv = __float2bfloat16(v);
            hiP.h[c16] = hv;
            loP.h[c16] = __float2bfloat16(v - __bfloat162float(hv));
        }
        __nv_bfloat16* dst = g_hn + ((size_t)b * N_ + tid*4 + j) * 1024 + g * CPG;
        *(uint4*)(dst)         = hiP.v[0]; *(uint4*)(dst + 8)         = hiP.v[1];
        *(uint4*)(dst + 512)   = loP.v[0]; *(uint4*)(dst + 512 + 8)   = loP.v[1];
    }
}

// ---------------------------------------------------------------------------
// HMMA GEMM mainloop: term-shared 16-chunk schedule, 2-stage cp.async,
// SINGLE barrier per chunk (wait -> sync -> issue(c+1) -> compute(c)).
//   c = 0..7 : stage {A-hi(c), A-lo(c), B-hi(c)}; both A terms vs one B tile
//   c = 8..15: stage {A-hi(c-8), B-lo(c-8)}      ; third term
// ---------------------------------------------------------------------------
#define SSTR 72
#define TILE_U (128 * SSTR)
#define STAGE_U (3 * TILE_U)
#define GEMM_SMEM (2 * STAGE_U * 2)        // 110592 B -> 2 CTA/SM

__device__ __forceinline__ void gemm_issue(__nv_bfloat16* stage,
                                           const __nv_bfloat16* Abase,
                                           const __nv_bfloat16* Bbase,
                                           int c, int ldRow, int ldSeg) {
    __nv_bfloat16* Ahi = stage;
    __nv_bfloat16* Alo = stage + TILE_U;
    __nv_bfloat16* Bt  = stage + 2 * TILE_U;
    if (c < 8) {
        int k0 = c * 64;
        #pragma unroll
        for (int rr = 0; rr < 4; rr++) {
            int row = ldRow + rr * 32;
            CPA(smem_u32(&Ahi[row * SSTR + ldSeg * 8]),
                Abase + (size_t)row * 1024 + k0 + ldSeg * 8);
            CPA(smem_u32(&Alo[row * SSTR + ldSeg * 8]),
                Abase + (size_t)row * 1024 + 512 + k0 + ldSeg * 8);
            CPA(smem_u32(&Bt[row * SSTR + ldSeg * 8]),
                Bbase + (size_t)row * 1024 + k0 + ldSeg * 8);
        }
    } else {
        int k0 = (c - 8) * 64;
        #pragma unroll
        for (int rr = 0; rr < 4; rr++) {
            int row = ldRow + rr * 32;
            CPA(smem_u32(&Ahi[row * SSTR + ldSeg * 8]),
                Abase + (size_t)row * 1024 + k0 + ldSeg * 8);
            CPA(smem_u32(&Bt[row * SSTR + ldSeg * 8]),
                Bbase + (size_t)row * 1024 + 512 + k0 + ldSeg * 8);
        }
    }
    CPCOMMIT();
}

__device__ __forceinline__ void gemm_mainloop(float acc[4][4][4],
                                              const __nv_bfloat16* __restrict__ Abase,
                                              const __nv_bfloat16* __restrict__ Bbase) {
    extern __shared__ __nv_bfloat16 dynsm[];
    __nv_bfloat16* stg[2] = { dynsm, dynsm + STAGE_U };

    int tid = threadIdx.x, wid = tid >> 5, lane = tid & 31;
    int wm = (wid >> 2) * 64;
    int wn = (wid & 3) * 32;
    int aRow = wm + (lane & 15), aCol = (lane >> 4) * 8;
    int bRowP = (lane & 7) + ((lane >> 4) * 8);
    int bColP = ((lane >> 3) & 1) * 8;
    int ldRow = tid >> 3;
    int ldSeg = tid & 7;

    gemm_issue(stg[0], Abase, Bbase, 0, ldRow, ldSeg);

    #pragma unroll 1
    for (int c = 0; c < 16; c++) {
        CPWAIT(0);
        __syncthreads();
        // Safe: all warps passed the barrier => all finished compute of c-1,
        // so buffer (c+1)&1 == (c-1)&1 is free to overwrite. Load of c+1
        // overlaps the compute of c below.
        if (c + 1 < 16)
            gemm_issue(stg[(c+1)&1], Abase, Bbase, c+1, ldRow, ldSeg);

        __nv_bfloat16* st = stg[c & 1];
        uint32_t smAhi = smem_u32(st);
        uint32_t smAlo = smem_u32(st + TILE_U);
        uint32_t smB   = smem_u32(st + 2 * TILE_U);
        bool dual = (c < 8);

        #pragma unroll
        for (int ks = 0; ks < 4; ks++) {
            uint32_t bf[2][4], afh[4][4];
            #pragma unroll
            for (int n2 = 0; n2 < 2; n2++)
                ldsm_x4(bf[n2], smB + ((wn + n2*16 + bRowP) * SSTR + ks*16 + bColP) * 2);
            #pragma unroll
            for (int mi = 0; mi < 4; mi++)
                ldsm_x4(afh[mi], smAhi + ((aRow + mi*16) * SSTR + ks*16 + aCol) * 2);
            #pragma unroll
            for (int mi = 0; mi < 4; mi++)
                #pragma unroll
                for (int n2 = 0; n2 < 2; n2++) {
                    mma_bf16(acc[mi][2*n2],   afh[mi], &bf[n2][0]);
                    mma_bf16(acc[mi][2*n2+1], afh[mi], &bf[n2][2]);
                }
            if (dual) {
                uint32_t afl[4][4];
                #pragma unroll
                for (int mi = 0; mi < 4; mi++)
                    ldsm_x4(afl[mi], smAlo + ((aRow + mi*16) * SSTR + ks*16 + aCol) * 2);
                #pragma unroll
                for (int mi = 0; mi < 4; mi++)
                    #pragma unroll
                    for (int n2 = 0; n2 < 2; n2++) {
                        mma_bf16(acc[mi][2*n2],   afl[mi], &bf[n2][0]);
                        mma_bf16(acc[mi][2*n2+1], afl[mi], &bf[n2][2]);
                    }
            }
        }
    }
}

// ---------------------------------------------------------------------------
// 2) QKV GEMM -> Q,K ext bf16 [b][h][n][128] (smem-staged coalesced stores);
//    V hi/lo planes [b][h][d][n]
// ---------------------------------------------------------------------------
#define ESTR 136

__global__ __launch_bounds__(256, 2) void qkv_gemm(const float* __restrict__ bias) {
    int n0 = blockIdx.x * 128, m0 = blockIdx.y * 128, b = blockIdx.z;

    float acc[4][4][4];
    #pragma unroll
    for (int i = 0; i < 4; i++)
        #pragma unroll
        for (int j = 0; j < 4; j++)
            { acc[i][j][0]=0.f; acc[i][j][1]=0.f; acc[i][j][2]=0.f; acc[i][j][3]=0.f; }

    gemm_mainloop(acc,
        g_wqkv + (size_t)m0 * 1024,
        g_hn + ((size_t)b * N_ + n0) * 1024);

    extern __shared__ __nv_bfloat16 dynsm[];
    int tid = threadIdx.x, wid = tid >> 5, lane = tid & 31;
    int wm = (wid >> 2) * 64, wn = (wid & 3) * 32;
    int s = m0 >> 9;

    if (s == 2) {
        #pragma unroll
        for (int mi = 0; mi < 4; mi++) {
            #pragma unroll
            for (int half = 0; half < 2; half++) {
                int o = m0 + wm + mi*16 + (lane >> 2) + half*8;
                int rem = o & 511, h = rem >> 6, d = rem & 63;
                float bv = bias[o];
                size_t vb = (((size_t)b * NH + h) * HD + d) * N_;
                #pragma unroll
                for (int ni = 0; ni < 4; ni++) {
                    int n = n0 + wn + ni*8 + (lane & 3)*2;
                    float v0 = acc[mi][ni][half*2 + 0] + bv;
                    float v1 = acc[mi][ni][half*2 + 1] + bv;
                    uint32_t hp = packbf2(v0, v1);
                    __nv_bfloat162 hb = *(__nv_bfloat162*)&hp;
                    uint32_t lp = packbf2(v0 - __bfloat162float(hb.x),
                                          v1 - __bfloat162float(hb.y));
                    *(uint32_t*)&g_vhi[vb + n] = hp;
                    *(uint32_t*)&g_vlo[vb + n] = lp;
                }
            }
        }
    } else {
        __syncthreads();   // mainloop has no trailing barrier; smem reuse below
        float scl = (s == 0) ? 0.125f : 1.0f;
        #pragma unroll
        for (int mi = 0; mi < 4; mi++) {
            #pragma unroll
            for (int half = 0; half < 2; half++) {
                int o = m0 + wm + mi*16 + (lane >> 2) + half*8;
                int hp = (o >> 6) & 1, d = o & 63;
                float bv = bias[o];
                __nv_bfloat16* Eb = dynsm + hp * (128 * ESTR);
                #pragma unroll
                for (int ni = 0; ni < 4; ni++) {
                    int nloc = wn + ni*8 + (lane & 3)*2;
                    float v0 = (acc[mi][ni][half*2 + 0] + bv) * scl;
                    float v1 = (acc[mi][ni][half*2 + 1] + bv) * scl;
                    __nv_bfloat16 h0 = __float2bfloat16(v0);
                    __nv_bfloat16 h1 = __float2bfloat16(v1);
                    Eb[nloc * ESTR + d]            = h0;
                    Eb[nloc * ESTR + 64 + d]       = __float2bfloat16(v0 - __bfloat162float(h0));
                    Eb[(nloc+1) * ESTR + d]        = h1;
                    Eb[(nloc+1) * ESTR + 64 + d]   = __float2bfloat16(v1 - __bfloat162float(h1));
                }
            }
        }
        __syncthreads();
        int h0g = (m0 & 511) >> 6;
        __nv_bfloat16* outp = (s == 0 ? g_qext : g_kext);
        #pragma unroll
        for (int i = 0; i < 16; i++) {
            int f = tid + i * 256;
            int hp = f >> 11, r = f & 2047, nloc = r >> 4, seg = r & 15;
            *(uint4*)(outp + (((size_t)b * NH + h0g + hp) * N_ + n0 + nloc) * 128 + seg * 8)
                = *(uint4*)(dynsm + hp * (128 * ESTR) + nloc * ESTR + seg * 8);
        }
    }
}

// ---------------------------------------------------------------------------
// 3) HMMA flash attention: 3-ring, streamed B fragments, 2 CTA/SM.
//    Softmax: deferred l-reduction + skip-rescale when max unchanged.
// ---------------------------------------------------------------------------
#define QSTR 136
#define ATTN_SMEM (52224 * 2)

__global__ __launch_bounds__(256, 2) void attn_kernel() {
    extern __shared__ __nv_bfloat16 dynsm[];
    __nv_bfloat16* Qh = dynsm;
    __nv_bfloat16* Kx[3] = { dynsm + 17408, dynsm + 34816, dynsm };
    __nv_bfloat16* Vx[3] = { dynsm + 26112, dynsm + 43520, dynsm + 8704 };

    int q0 = blockIdx.x * 128;
    int bh = blockIdx.y;
    const __nv_bfloat16* qg = g_qext + (size_t)bh * N_ * 128;
    const __nv_bfloat16* kg = g_kext + (size_t)bh * N_ * 128;
    const __nv_bfloat16* vhi = g_vhi + (size_t)bh * HD * N_;
    const __nv_bfloat16* vlo = g_vlo + (size_t)bh * HD * N_;

    int tid = threadIdx.x, w = tid >> 5, lane = tid & 31;

    #pragma unroll
    for (int i = 0; i < 8; i++) {
        int idx = tid + i * 256;
        int row = idx >> 4, seg = idx & 15;
        CPA(smem_u32(&Qh[row * QSTR + seg * 8]), qg + (size_t)(q0 + row) * 128 + seg * 8);
    }
    CPCOMMIT();

    #pragma unroll
    for (int st = 0; st < 2; st++) {
        int nb = st * 64;
        #pragma unroll
        for (int i = 0; i < 4; i++) {
            int idx = tid + i * 256;
            int row = idx >> 4, seg = idx & 15;
            CPA(smem_u32(&Kx[st][row * QSTR + seg * 8]),
                kg + (size_t)(nb + row) * 128 + seg * 8);
        }
        #pragma unroll
        for (int i = 0; i < 4; i++) {
            int idx = tid + i * 256;
            int d = idx >> 4, seg = idx & 15;
            const __nv_bfloat16* src = (seg < 8 ? vhi : vlo) + (size_t)d * N_ + nb + (seg & 7) * 8;
            CPA(smem_u32(&Vx[st][d * QSTR + seg * 8]), src);
        }
        CPCOMMIT();
    }

    CPWAIT(2);
    __syncthreads();
    uint32_t qbase = smem_u32(Qh);
    int ar = w * 16 + (lane & 15);
    int ac = (lane >> 4) * 8;
    uint32_t qh[4][4], ql[4][4];
    #pragma unroll
    for (int ks = 0; ks < 4; ks++) {
        ldsm_x4(qh[ks], qbase + (ar * QSTR + ks * 16 + ac) * 2);
        ldsm_x4(ql[ks], qbase + (ar * QSTR + 64 + ks * 16 + ac) * 2);
    }
    __syncthreads();

    float oacc[8][4];
    #pragma unroll
    for (int i = 0; i < 8; i++)
        { oacc[i][0]=0.f; oacc[i][1]=0.f; oacc[i][2]=0.f; oacc[i][3]=0.f; }
    float m0 = -1e30f, m1 = -1e30f;
    float l0p = 0.f, l1p = 0.f;

    int bRowP = (lane & 7) + ((lane >> 4) * 8);
    int bColP = ((lane >> 3) & 1) * 8;

    #pragma unroll 1
    for (int ch = 0; ch < 16; ch++) {
        if (ch < 14) CPWAIT(1); else CPWAIT(0);
        __syncthreads();

        if (ch + 2 < 16) {
            int st = (ch + 2) % 3, nb = (ch + 2) * 64;
            #pragma unroll
            for (int i = 0; i < 4; i++) {
                int idx = tid + i * 256;
                int row = idx >> 4, seg = idx & 15;
                CPA(smem_u32(&Kx[st][row * QSTR + seg * 8]),
                    kg + (size_t)(nb + row) * 128 + seg * 8);
            }
            #pragma unroll
            for (int i = 0; i < 4; i++) {
                int idx = tid + i * 256;
                int d = idx >> 4, seg = idx & 15;
                const __nv_bfloat16* src = (seg < 8 ? vhi : vlo) + (size_t)d * N_ + nb + (seg & 7) * 8;
                CPA(smem_u32(&Vx[st][d * QSTR + seg * 8]), src);
            }
            CPCOMMIT();
        }

        uint32_t kbase = smem_u32(Kx[ch % 3]);
        uint32_t vbase = smem_u32(Vx[ch % 3]);

        float sacc[8][4];
        #pragma unroll
        for (int i = 0; i < 8; i++)
            { sacc[i][0]=0.f; sacc[i][1]=0.f; sacc[i][2]=0.f; sacc[i][3]=0.f; }

        #pragma unroll
        for (int n2 = 0; n2 < 4; n2++) {
            #pragma unroll
            for (int ks = 0; ks < 4; ks++) {
                uint32_t kb[4];
                ldsm_x4(kb, kbase + ((n2*16 + bRowP) * QSTR + ks*16 + bColP) * 2);
                mma_bf16(sacc[2*n2],   qh[ks], &kb[0]);
                mma_bf16(sacc[2*n2+1], qh[ks], &kb[2]);
                mma_bf16(sacc[2*n2],   ql[ks], &kb[0]);
                mma_bf16(sacc[2*n2+1], ql[ks], &kb[2]);
            }
            #pragma unroll
            for (int ks = 0; ks < 4; ks++) {
                uint32_t kb[4];
                ldsm_x4(kb, kbase + ((n2*16 + bRowP) * QSTR + 64 + ks*16 + bColP) * 2);
                mma_bf16(sacc[2*n2],   qh[ks], &kb[0]);
                mma_bf16(sacc[2*n2+1], qh[ks], &kb[2]);
            }
        }

        float mx0 = -1e30f, mx1 = -1e30f;
        #pragma unroll
        for (int nf = 0; nf < 8; nf++) {
            mx0 = fmaxf(mx0, fmaxf(sacc[nf][0], sacc[nf][1]));
            mx1 = fmaxf(mx1, fmaxf(sacc[nf][2], sacc[nf][3]));
        }
        mx0 = fmaxf(mx0, __shfl_xor_sync(0xffffffffu, mx0, 1));
        mx0 = fmaxf(mx0, __shfl_xor_sync(0xffffffffu, mx0, 2));
        mx1 = fmaxf(mx1, __shfl_xor_sync(0xffffffffu, mx1, 1));
        mx1 = fmaxf(mx1, __shfl_xor_sync(0xffffffffu, mx1, 2));
        float mn0 = fmaxf(m0, mx0), mn1 = fmaxf(m1, mx1);
        float f0 = ex2((m0 - mn0) * LOG2E), f1 = ex2((m1 - mn1) * LOG2E);

        if (!__all_sync(0xffffffffu, (f0 == 1.f) && (f1 == 1.f))) {
            l0p *= f0; l1p *= f1;
            #pragma unroll
            for (int df = 0; df < 8; df++) {
                oacc[df][0] *= f0; oacc[df][1] *= f0;
                oacc[df][2] *= f1; oacc[df][3] *= f1;
            }
        }
        m0 = mn0; m1 = mn1;

        #pragma unroll
        for (int nf = 0; nf < 8; nf++) {
            sacc[nf][0] = ex2((sacc[nf][0] - mn0) * LOG2E);
            sacc[nf][1] = ex2((sacc[nf][1] - mn0) * LOG2E);
            sacc[nf][2] = ex2((sacc[nf][2] - mn1) * LOG2E);
            sacc[nf][3] = ex2((sacc[nf][3] - mn1) * LOG2E);
            l0p += sacc[nf][0] + sacc[nf][1];
            l1p += sacc[nf][2] + sacc[nf][3];
        }

        uint32_t phi[4][4], plo[4][4];
        #pragma unroll
        for (int ks = 0; ks < 4; ks++) {
            int j = 2 * ks;
            float p00 = sacc[j][0],   p01 = sacc[j][1];
            float p02 = sacc[j][2],   p03 = sacc[j][3];
            float p10 = sacc[j+1][0], p11 = sacc[j+1][1];
            float p12 = sacc[j+1][2], p13 = sacc[j+1][3];
            phi[ks][0] = packbf2(p00, p01);
            phi[ks][1] = packbf2(p02, p03);
            phi[ks][2] = packbf2(p10, p11);
            phi[ks][3] = packbf2(p12, p13);
            __nv_bfloat162* hp;
            hp = (__nv_bfloat162*)&phi[ks][0];
            plo[ks][0] = packbf2(p00 - __bfloat162float(hp->x), p01 - __bfloat162float(hp->y));
            hp = (__nv_bfloat162*)&phi[ks][1];
            plo[ks][1] = packbf2(p02 - __bfloat162float(hp->x), p03 - __bfloat162float(hp->y));
            hp = (__nv_bfloat162*)&phi[ks][2];
            plo[ks][2] = packbf2(p10 - __bfloat162float(hp->x), p11 - __bfloat162float(hp->y));
            hp = (__nv_bfloat162*)&phi[ks][3];
            plo[ks][3] = packbf2(p12 - __bfloat162float(hp->x), p13 - __bfloat162float(hp->y));
        }

        #pragma unroll
        for (int d2 = 0; d2 < 4; d2++) {
            #pragma unroll
            for (int ks = 0; ks < 4; ks++) {
                uint32_t vb[4];
                ldsm_x4(vb, vbase + ((d2*16 + bRowP) * QSTR + ks*16 + bColP) * 2);
                mma_bf16(oacc[2*d2],   phi[ks], &vb[0]);
                mma_bf16(oacc[2*d2+1], phi[ks], &vb[2]);
                mma_bf16(oacc[2*d2],   plo[ks], &vb[0]);
                mma_bf16(oacc[2*d2+1], plo[ks], &vb[2]);
            }
            #pragma unroll
            for (int ks = 0; ks < 4; ks++) {
                uint32_t vb[4];
                ldsm_x4(vb, vbase + ((d2*16 + bRowP) * QSTR + 64 + ks*16 + bColP) * 2);
                mma_bf16(oacc[2*d2],   phi[ks], &vb[0]);
                mma_bf16(oacc[2*d2+1], phi[ks], &vb[2]);
            }
        }
    }

    l0p += __shfl_xor_sync(0xffffffffu, l0p, 1);
    l0p += __shfl_xor_sync(0xffffffffu, l0p, 2);
    l1p += __shfl_xor_sync(0xffffffffu, l1p, 1);
    l1p += __shfl_xor_sync(0xffffffffu, l1p, 2);

    float inv0 = 1.f / l0p, inv1 = 1.f / l1p;
    int b = bh >> 3, h = bh & 7;
    int row0 = q0 + w * 16 + (lane >> 2);
    #pragma unroll
    for (int df = 0; df < 8; df++) {
        int chn = h * HD + df * 8 + (lane & 3) * 2;
        #pragma unroll
        for (int r = 0; r < 2; r++) {
            int row = row0 + r * 8;
            float v0 = oacc[df][r*2 + 0] * (r ? inv1 : inv0);
            float v1 = oacc[df][r*2 + 1] * (r ? inv1 : inv0);
            uint32_t hp = packbf2(v0, v1);
            __nv_bfloat162 hb = *(__nv_bfloat162*)&hp;
            uint32_t lp = packbf2(v0 - __bfloat162float(hb.x), v1 - __bfloat162float(hb.y));
            size_t eb = ((size_t)b * N_ + row) * 1024 + chn;
            *(uint32_t*)&g_obuf[eb]       = hp;
            *(uint32_t*)&g_obuf[eb + 512] = lp;
        }
    }
}

// ---------------------------------------------------------------------------
// 4) Proj GEMM + bias + residual -> out[b][c][n]
// ---------------------------------------------------------------------------
__global__ __launch_bounds__(256, 2) void proj_gemm(const float* __restrict__ bias,
                                                    const float* __restrict__ x,
                                                    float* __restrict__ out) {
    int n0 = blockIdx.x * 128, m0 = blockIdx.y * 128, b = blockIdx.z;

    float acc[4][4][4];
    #pragma unroll
    for (int i = 0; i < 4; i++)
        #pragma unroll
        for (int j = 0; j < 4; j++)
            { acc[i][j][0]=0.f; acc[i][j][1]=0.f; acc[i][j][2]=0.f; acc[i][j][3]=0.f; }

    gemm_mainloop(acc,
        g_wproj + (size_t)m0 * 1024,
        g_obuf + ((size_t)b * N_ + n0) * 1024);

    int wid = threadIdx.x >> 5, lane = threadIdx.x & 31;
    int wm = (wid >> 2) * 64, wn = (wid & 3) * 32;

    #pragma unroll
    for (int mi = 0; mi < 4; mi++) {
        #pragma unroll
        for (int half = 0; half < 2; half++) {
            int chn = m0 + wm + mi*16 + (lane >> 2) + half*8;
            float bv = bias[chn];
            size_t rowbase = ((size_t)b * C_ + chn) * N_;
            #pragma unroll
            for (int ni = 0; ni < 4; ni++) {
                int n = n0 + wn + ni*8 + (lane & 3)*2;
                float2 xv = *(const float2*)&x[rowbase + n];
                float2 v;
                v.x = acc[mi][ni][half*2 + 0] + bv + xv.x;
                v.y = acc[mi][ni][half*2 + 1] + bv + xv.y;
                *(float2*)&out[rowbase + n] = v;
            }
        }
    }
}

// ---------------------------------------------------------------------------
extern "C" void kernel_launch(void* const* d_in, const int* in_sizes, int n_in,
                              void* d_out, int out_size) {
    const float* x      = (const float*)d_in[0];
    const float* norm_w = (const float*)d_in[1];
    const float* norm_b = (const float*)d_in[2];
    const float* qkv_w  = (const float*)d_in[3];
    const float* qkv_b  = (const float*)d_in[4];
    const float* proj_w = (const float*)d_in[5];
    const float* proj_b = (const float*)d_in[6];
    float* out = (float*)d_out;

    cudaFuncSetAttribute(qkv_gemm, cudaFuncAttributeMaxDynamicSharedMemorySize, GEMM_SMEM);
    cudaFuncSetAttribute(proj_gemm, cudaFuncAttributeMaxDynamicSharedMemorySize, GEMM_SMEM);
    cudaFuncSetAttribute(attn_kernel, cudaFuncAttributeMaxDynamicSharedMemorySize, ATTN_SMEM);

    convw_kernel<<<4 * C_, 128>>>(qkv_w, proj_w);
    gn_kernel<<<B_ * G_, 256>>>(x, norm_w, norm_b);
    qkv_gemm<<<dim3(N_ / 128, (3 * C_) / 128, B_), 256, GEMM_SMEM>>>(qkv_b);
    attn_kernel<<<dim3(N_ / 128, B_ * NH), 256, ATTN_SMEM>>>();
    proj_gemm<<<dim3(N_ / 128, C_ / 128, B_), 256, GEMM_SMEM>>>(proj_b, x, out);
}

// round 17
// speedup vs baseline: 1.5388x; 1.5388x over previous
#include <cuda_runtime.h>
#include <cuda_bf16.h>
#include <cstdint>

#define B_   16
#define C_   512
#define NH   8
#define HD   64
#define N_   1024
#define G_   32
#define CPG  16
#define EPSV 1e-5f
#define LOG2E 1.4426950408889634f

// ---------------- scratch (device globals; no allocation allowed) -----------
__device__ __nv_bfloat16 g_qext[(size_t)B_ * NH * N_ * 128];   // [b][h][n][hi64|lo64], pre-scaled
__device__ __nv_bfloat16 g_kext[(size_t)B_ * NH * N_ * 128];   // [b][h][n][hi64|lo64]
__device__ __nv_bfloat16 g_vhi[(size_t)B_ * NH * HD * N_];     // [b][h][d][n]
__device__ __nv_bfloat16 g_vlo[(size_t)B_ * NH * HD * N_];
__device__ __nv_bfloat16 g_hn[(size_t)B_ * N_ * 1024];         // [b][n][hi512|lo512]
__device__ __nv_bfloat16 g_obuf[(size_t)B_ * N_ * 1024];       // [b][n][hi512|lo512]
__device__ __nv_bfloat16 g_wqkv[(size_t)(3*C_) * 1024];        // [o][hi512|lo512]
__device__ __nv_bfloat16 g_wproj[(size_t)C_ * 1024];           // [o][hi512|lo512]

// ---------------- PTX helpers (baseline-safe for compute_103) ---------------
__device__ __forceinline__ uint32_t smem_u32(const void* p) {
    uint32_t a;
    asm("{ .reg .u64 t; cvta.to.shared.u64 t, %1; cvt.u32.u64 %0, t; }" : "=r"(a) : "l"(p));
    return a;
}
__device__ __forceinline__ void ldsm_x4(uint32_t* r, uint32_t addr) {
    asm volatile("ldmatrix.sync.aligned.m8n8.x4.shared.b16 {%0,%1,%2,%3}, [%4];"
                 : "=r"(r[0]), "=r"(r[1]), "=r"(r[2]), "=r"(r[3]) : "r"(addr));
}
__device__ __forceinline__ void mma_bf16(float* c, const uint32_t* a, const uint32_t* b) {
    asm volatile("mma.sync.aligned.m16n8k16.row.col.f32.bf16.bf16.f32 "
                 "{%0,%1,%2,%3}, {%4,%5,%6,%7}, {%8,%9}, {%0,%1,%2,%3};"
                 : "+f"(c[0]), "+f"(c[1]), "+f"(c[2]), "+f"(c[3])
                 : "r"(a[0]), "r"(a[1]), "r"(a[2]), "r"(a[3]), "r"(b[0]), "r"(b[1]));
}
__device__ __forceinline__ float ex2(float x) {
    float r; asm("ex2.approx.f32 %0, %1;" : "=f"(r) : "f"(x)); return r;
}
__device__ __forceinline__ uint32_t packbf2(float a, float b) {
    __nv_bfloat162 t; t.x = __float2bfloat16(a); t.y = __float2bfloat16(b);
    return *(uint32_t*)&t;
}
#define CPA(dst, src) \
    asm volatile("cp.async.cg.shared.global [%0], [%1], 16;" :: "r"(dst), "l"(src))
#define CPCOMMIT() asm volatile("cp.async.commit_group;")
#define CPWAIT(n)  asm volatile("cp.async.wait_group %0;" :: "n"(n))

// ---------------------------------------------------------------------------
// 0) Weight split: w[o][c] fp32 -> 2-plane [o][hi512|lo512]
// ---------------------------------------------------------------------------
__global__ void convw_kernel(const float* __restrict__ wq, const float* __restrict__ wp) {
    int r = blockIdx.x;
    const float* src = (r < 3*C_) ? wq + (size_t)r * C_ : wp + (size_t)(r - 3*C_) * C_;
    __nv_bfloat16* dst = (r < 3*C_) ? g_wqkv + (size_t)r * 1024
                                    : g_wproj + (size_t)(r - 3*C_) * 1024;
    for (int c = threadIdx.x; c < C_; c += 128) {
        float v = src[c];
        __nv_bfloat16 hi = __float2bfloat16(v);
        dst[c]       = hi;
        dst[512 + c] = __float2bfloat16(v - __bfloat162float(hi));
    }
}

// ---------------------------------------------------------------------------
// 1) GroupNorm + transpose + bf16 split -> g_hn [b][n][hi512|lo512]
//    Reduction: warp-shuffle partials + one smem stage + one sync.
// ---------------------------------------------------------------------------
__global__ __launch_bounds__(256) void gn_kernel(const float* __restrict__ x,
                                                 const float* __restrict__ w,
                                                 const float* __restrict__ bb) {
    int bg = blockIdx.x;
    int g = bg & (G_ - 1), b = bg >> 5;
    const float4* x4 = (const float4*)(x + (size_t)bg * CPG * N_);
    int tid = threadIdx.x;

    float s = 0.f, s2 = 0.f;
    #pragma unroll
    for (int i = 0; i < 16; i++) {
        float4 v = x4[tid + i * 256];
        s  += v.x + v.y + v.z + v.w;
        s2 += v.x*v.x + v.y*v.y + v.z*v.z + v.w*v.w;
    }
    // warp reduce
    #pragma unroll
    for (int off = 16; off > 0; off >>= 1) {
        s  += __shfl_xor_sync(0xffffffffu, s, off);
        s2 += __shfl_xor_sync(0xffffffffu, s2, off);
    }
    __shared__ float ws[8], ws2[8];
    __shared__ float bstat[2];
    if ((tid & 31) == 0) { ws[tid >> 5] = s; ws2[tid >> 5] = s2; }
    __syncthreads();
    if (tid == 0) {
        float ts = 0.f, ts2 = 0.f;
        #pragma unroll
        for (int i = 0; i < 8; i++) { ts += ws[i]; ts2 += ws2[i]; }
        float mean = ts * (1.f/16384.f);
        float var  = ts2 * (1.f/16384.f) - mean*mean;
        bstat[0] = mean;
        bstat[1] = rsqrtf(var + EPSV);
    }
    __syncthreads();
    float mean = bstat[0], rstd = bstat[1];

    float sc[CPG], sh[CPG];
    #pragma unroll
    for (int c16 = 0; c16 < CPG; c16++) {
        int c = g*CPG + c16;
        sc[c16] = rstd * w[c];
        sh[c16] = bb[c] - mean * sc[c16];
    }

    float4 vals[CPG];
    #pragma unroll
    for (int c16 = 0; c16 < CPG; c16++) {
        float4 v = x4[c16 * 256 + tid];
        vals[c16].x = v.x*sc[c16]+sh[c16]; vals[c16].y = v.y*sc[c16]+sh[c16];
        vals[c16].z = v.z*sc[c16]+sh[c16]; vals[c16].w = v.w*sc[c16]+sh[c16];
    }
    union Pack { __nv_bfloat16 h[CPG]; uint4 v[2]; };
    #pragma unroll
    for (int j = 0; j < 4; j++) {
        Pack hiP, loP;
        #pragma unroll
        for (int c16 = 0; c16 < CPG; c16++) {
            float v = j == 0 ? vals[c16].x : j == 1 ? vals[c16].y
                    : j == 2 ? vals[c16].z : vals[c16].w;
            __nv_bfloat16 hv = __float2bfloat16(v);
            hiP.h[c16] = hv;
            loP.h[c16] = __float2bfloat16(v - __bfloat162float(hv));
        }
        __nv_bfloat16* dst = g_hn + ((size_t)b * N_ + tid*4 + j) * 1024 + g * CPG;
        *(uint4*)(dst)         = hiP.v[0]; *(uint4*)(dst + 8)         = hiP.v[1];
        *(uint4*)(dst + 512)   = loP.v[0]; *(uint4*)(dst + 512 + 8)   = loP.v[1];
    }
}

// ---------------------------------------------------------------------------
// HMMA GEMM mainloop: term-shared 16-chunk schedule, 2-stage cp.async,
// R11-proven ordering: issue(c+1) -> CPWAIT(1) -> sync -> compute -> sync.
//   c = 0..7 : stage {A-hi(c), A-lo(c), B-hi(c)}; both A terms vs one B tile
//   c = 8..15: stage {A-hi(c-8), B-lo(c-8)}      ; third term
// ---------------------------------------------------------------------------
#define SSTR 72
#define TILE_U (128 * SSTR)
#define STAGE_U (3 * TILE_U)
#define GEMM_SMEM (2 * STAGE_U * 2)        // 110592 B -> 2 CTA/SM

__device__ __forceinline__ void gemm_issue(__nv_bfloat16* stage,
                                           const __nv_bfloat16* Abase,
                                           const __nv_bfloat16* Bbase,
                                           int c, int ldRow, int ldSeg) {
    __nv_bfloat16* Ahi = stage;
    __nv_bfloat16* Alo = stage + TILE_U;
    __nv_bfloat16* Bt  = stage + 2 * TILE_U;
    if (c < 8) {
        int k0 = c * 64;
        #pragma unroll
        for (int rr = 0; rr < 4; rr++) {
            int row = ldRow + rr * 32;
            CPA(smem_u32(&Ahi[row * SSTR + ldSeg * 8]),
                Abase + (size_t)row * 1024 + k0 + ldSeg * 8);
            CPA(smem_u32(&Alo[row * SSTR + ldSeg * 8]),
                Abase + (size_t)row * 1024 + 512 + k0 + ldSeg * 8);
            CPA(smem_u32(&Bt[row * SSTR + ldSeg * 8]),
                Bbase + (size_t)row * 1024 + k0 + ldSeg * 8);
        }
    } else {
        int k0 = (c - 8) * 64;
        #pragma unroll
        for (int rr = 0; rr < 4; rr++) {
            int row = ldRow + rr * 32;
            CPA(smem_u32(&Ahi[row * SSTR + ldSeg * 8]),
                Abase + (size_t)row * 1024 + k0 + ldSeg * 8);
            CPA(smem_u32(&Bt[row * SSTR + ldSeg * 8]),
                Bbase + (size_t)row * 1024 + 512 + k0 + ldSeg * 8);
        }
    }
    CPCOMMIT();
}

__device__ __forceinline__ void gemm_mainloop(float acc[4][4][4],
                                              const __nv_bfloat16* __restrict__ Abase,
                                              const __nv_bfloat16* __restrict__ Bbase) {
    extern __shared__ __nv_bfloat16 dynsm[];
    __nv_bfloat16* stg[2] = { dynsm, dynsm + STAGE_U };

    int tid = threadIdx.x, wid = tid >> 5, lane = tid & 31;
    int wm = (wid >> 2) * 64;
    int wn = (wid & 3) * 32;
    int aRow = wm + (lane & 15), aCol = (lane >> 4) * 8;
    int bRowP = (lane & 7) + ((lane >> 4) * 8);
    int bColP = ((lane >> 3) & 1) * 8;
    int ldRow = tid >> 3;
    int ldSeg = tid & 7;

    gemm_issue(stg[0], Abase, Bbase, 0, ldRow, ldSeg);

    #pragma unroll 1
    for (int c = 0; c < 16; c++) {
        if (c + 1 < 16) {
            gemm_issue(stg[(c+1)&1], Abase, Bbase, c+1, ldRow, ldSeg);
            CPWAIT(1);
        } else {
            CPWAIT(0);
        }
        __syncthreads();

        __nv_bfloat16* st = stg[c & 1];
        uint32_t smAhi = smem_u32(st);
        uint32_t smAlo = smem_u32(st + TILE_U);
        uint32_t smB   = smem_u32(st + 2 * TILE_U);
        bool dual = (c < 8);

        #pragma unroll
        for (int ks = 0; ks < 4; ks++) {
            uint32_t bf[2][4], afh[4][4];
            #pragma unroll
            for (int n2 = 0; n2 < 2; n2++)
                ldsm_x4(bf[n2], smB + ((wn + n2*16 + bRowP) * SSTR + ks*16 + bColP) * 2);
            #pragma unroll
            for (int mi = 0; mi < 4; mi++)
                ldsm_x4(afh[mi], smAhi + ((aRow + mi*16) * SSTR + ks*16 + aCol) * 2);
            #pragma unroll
            for (int mi = 0; mi < 4; mi++)
                #pragma unroll
                for (int n2 = 0; n2 < 2; n2++) {
                    mma_bf16(acc[mi][2*n2],   afh[mi], &bf[n2][0]);
                    mma_bf16(acc[mi][2*n2+1], afh[mi], &bf[n2][2]);
                }
            if (dual) {
                uint32_t afl[4][4];
                #pragma unroll
                for (int mi = 0; mi < 4; mi++)
                    ldsm_x4(afl[mi], smAlo + ((aRow + mi*16) * SSTR + ks*16 + aCol) * 2);
                #pragma unroll
                for (int mi = 0; mi < 4; mi++)
                    #pragma unroll
                    for (int n2 = 0; n2 < 2; n2++) {
                        mma_bf16(acc[mi][2*n2],   afl[mi], &bf[n2][0]);
                        mma_bf16(acc[mi][2*n2+1], afl[mi], &bf[n2][2]);
                    }
            }
        }
        __syncthreads();
    }
}

// ---------------------------------------------------------------------------
// 2) QKV GEMM -> Q,K ext bf16 [b][h][n][128] (smem-staged coalesced stores);
//    V hi/lo planes [b][h][d][n]
// ---------------------------------------------------------------------------
#define ESTR 136

__global__ __launch_bounds__(256, 2) void qkv_gemm(const float* __restrict__ bias) {
    int n0 = blockIdx.x * 128, m0 = blockIdx.y * 128, b = blockIdx.z;

    float acc[4][4][4];
    #pragma unroll
    for (int i = 0; i < 4; i++)
        #pragma unroll
        for (int j = 0; j < 4; j++)
            { acc[i][j][0]=0.f; acc[i][j][1]=0.f; acc[i][j][2]=0.f; acc[i][j][3]=0.f; }

    gemm_mainloop(acc,
        g_wqkv + (size_t)m0 * 1024,
        g_hn + ((size_t)b * N_ + n0) * 1024);

    extern __shared__ __nv_bfloat16 dynsm[];
    int tid = threadIdx.x, wid = tid >> 5, lane = tid & 31;
    int wm = (wid >> 2) * 64, wn = (wid & 3) * 32;
    int s = m0 >> 9;

    if (s == 2) {
        #pragma unroll
        for (int mi = 0; mi < 4; mi++) {
            #pragma unroll
            for (int half = 0; half < 2; half++) {
                int o = m0 + wm + mi*16 + (lane >> 2) + half*8;
                int rem = o & 511, h = rem >> 6, d = rem & 63;
                float bv = bias[o];
                size_t vb = (((size_t)b * NH + h) * HD + d) * N_;
                #pragma unroll
                for (int ni = 0; ni < 4; ni++) {
                    int n = n0 + wn + ni*8 + (lane & 3)*2;
                    float v0 = acc[mi][ni][half*2 + 0] + bv;
                    float v1 = acc[mi][ni][half*2 + 1] + bv;
                    uint32_t hp = packbf2(v0, v1);
                    __nv_bfloat162 hb = *(__nv_bfloat162*)&hp;
                    uint32_t lp = packbf2(v0 - __bfloat162float(hb.x),
                                          v1 - __bfloat162float(hb.y));
                    *(uint32_t*)&g_vhi[vb + n] = hp;
                    *(uint32_t*)&g_vlo[vb + n] = lp;
                }
            }
        }
    } else {
        float scl = (s == 0) ? 0.125f : 1.0f;
        #pragma unroll
        for (int mi = 0; mi < 4; mi++) {
            #pragma unroll
            for (int half = 0; half < 2; half++) {
                int o = m0 + wm + mi*16 + (lane >> 2) + half*8;
                int hp = (o >> 6) & 1, d = o & 63;
                float bv = bias[o];
                __nv_bfloat16* Eb = dynsm + hp * (128 * ESTR);
                #pragma unroll
                for (int ni = 0; ni < 4; ni++) {
                    int nloc = wn + ni*8 + (lane & 3)*2;
                    float v0 = (acc[mi][ni][half*2 + 0] + bv) * scl;
                    float v1 = (acc[mi][ni][half*2 + 1] + bv) * scl;
                    __nv_bfloat16 h0 = __float2bfloat16(v0);
                    __nv_bfloat16 h1 = __float2bfloat16(v1);
                    Eb[nloc * ESTR + d]            = h0;
                    Eb[nloc * ESTR + 64 + d]       = __float2bfloat16(v0 - __bfloat162float(h0));
                    Eb[(nloc+1) * ESTR + d]        = h1;
                    Eb[(nloc+1) * ESTR + 64 + d]   = __float2bfloat16(v1 - __bfloat162float(h1));
                }
            }
        }
        __syncthreads();
        int h0g = (m0 & 511) >> 6;
        __nv_bfloat16* outp = (s == 0 ? g_qext : g_kext);
        #pragma unroll
        for (int i = 0; i < 16; i++) {
            int f = tid + i * 256;
            int hp = f >> 11, r = f & 2047, nloc = r >> 4, seg = r & 15;
            *(uint4*)(outp + (((size_t)b * NH + h0g + hp) * N_ + n0 + nloc) * 128 + seg * 8)
                = *(uint4*)(dynsm + hp * (128 * ESTR) + nloc * ESTR + seg * 8);
        }
    }
}

// ---------------------------------------------------------------------------
// 3) HMMA flash attention: 3-ring, streamed B fragments, 2 CTA/SM.
//    Softmax: deferred l-reduction + skip-rescale when max unchanged.
// ---------------------------------------------------------------------------
#define QSTR 136
#define ATTN_SMEM (52224 * 2)

__global__ __launch_bounds__(256, 2) void attn_kernel() {
    extern __shared__ __nv_bfloat16 dynsm[];
    __nv_bfloat16* Qh = dynsm;
    __nv_bfloat16* Kx[3] = { dynsm + 17408, dynsm + 34816, dynsm };
    __nv_bfloat16* Vx[3] = { dynsm + 26112, dynsm + 43520, dynsm + 8704 };

    int q0 = blockIdx.x * 128;
    int bh = blockIdx.y;
    const __nv_bfloat16* qg = g_qext + (size_t)bh * N_ * 128;
    const __nv_bfloat16* kg = g_kext + (size_t)bh * N_ * 128;
    const __nv_bfloat16* vhi = g_vhi + (size_t)bh * HD * N_;
    const __nv_bfloat16* vlo = g_vlo + (size_t)bh * HD * N_;

    int tid = threadIdx.x, w = tid >> 5, lane = tid & 31;

    #pragma unroll
    for (int i = 0; i < 8; i++) {
        int idx = tid + i * 256;
        int row = idx >> 4, seg = idx & 15;
        CPA(smem_u32(&Qh[row * QSTR + seg * 8]), qg + (size_t)(q0 + row) * 128 + seg * 8);
    }
    CPCOMMIT();

    #pragma unroll
    for (int st = 0; st < 2; st++) {
        int nb = st * 64;
        #pragma unroll
        for (int i = 0; i < 4; i++) {
            int idx = tid + i * 256;
            int row = idx >> 4, seg = idx & 15;
            CPA(smem_u32(&Kx[st][row * QSTR + seg * 8]),
                kg + (size_t)(nb + row) * 128 + seg * 8);
        }
        #pragma unroll
        for (int i = 0; i < 4; i++) {
            int idx = tid + i * 256;
            int d = idx >> 4, seg = idx & 15;
            const __nv_bfloat16* src = (seg < 8 ? vhi : vlo) + (size_t)d * N_ + nb + (seg & 7) * 8;
            CPA(smem_u32(&Vx[st][d * QSTR + seg * 8]), src);
        }
        CPCOMMIT();
    }

    CPWAIT(2);
    __syncthreads();
    uint32_t qbase = smem_u32(Qh);
    int ar = w * 16 + (lane & 15);
    int ac = (lane >> 4) * 8;
    uint32_t qh[4][4], ql[4][4];
    #pragma unroll
    for (int ks = 0; ks < 4; ks++) {
        ldsm_x4(qh[ks], qbase + (ar * QSTR + ks * 16 + ac) * 2);
        ldsm_x4(ql[ks], qbase + (ar * QSTR + 64 + ks * 16 + ac) * 2);
    }
    __syncthreads();

    float oacc[8][4];
    #pragma unroll
    for (int i = 0; i < 8; i++)
        { oacc[i][0]=0.f; oacc[i][1]=0.f; oacc[i][2]=0.f; oacc[i][3]=0.f; }
    float m0 = -1e30f, m1 = -1e30f;
    float l0p = 0.f, l1p = 0.f;

    int bRowP = (lane & 7) + ((lane >> 4) * 8);
    int bColP = ((lane >> 3) & 1) * 8;

    #pragma unroll 1
    for (int ch = 0; ch < 16; ch++) {
        if (ch < 14) CPWAIT(1); else CPWAIT(0);
        __syncthreads();

        if (ch + 2 < 16) {
            int st = (ch + 2) % 3, nb = (ch + 2) * 64;
            #pragma unroll
            for (int i = 0; i < 4; i++) {
                int idx = tid + i * 256;
                int row = idx >> 4, seg = idx & 15;
                CPA(smem_u32(&Kx[st][row * QSTR + seg * 8]),
                    kg + (size_t)(nb + row) * 128 + seg * 8);
            }
            #pragma unroll
            for (int i = 0; i < 4; i++) {
                int idx = tid + i * 256;
                int d = idx >> 4, seg = idx & 15;
                const __nv_bfloat16* src = (seg < 8 ? vhi : vlo) + (size_t)d * N_ + nb + (seg & 7) * 8;
                CPA(smem_u32(&Vx[st][d * QSTR + seg * 8]), src);
            }
            CPCOMMIT();
        }

        uint32_t kbase = smem_u32(Kx[ch % 3]);
        uint32_t vbase = smem_u32(Vx[ch % 3]);

        float sacc[8][4];
        #pragma unroll
        for (int i = 0; i < 8; i++)
            { sacc[i][0]=0.f; sacc[i][1]=0.f; sacc[i][2]=0.f; sacc[i][3]=0.f; }

        #pragma unroll
        for (int n2 = 0; n2 < 4; n2++) {
            #pragma unroll
            for (int ks = 0; ks < 4; ks++) {
                uint32_t kb[4];
                ldsm_x4(kb, kbase + ((n2*16 + bRowP) * QSTR + ks*16 + bColP) * 2);
                mma_bf16(sacc[2*n2],   qh[ks], &kb[0]);
                mma_bf16(sacc[2*n2+1], qh[ks], &kb[2]);
                mma_bf16(sacc[2*n2],   ql[ks], &kb[0]);
                mma_bf16(sacc[2*n2+1], ql[ks], &kb[2]);
            }
            #pragma unroll
            for (int ks = 0; ks < 4; ks++) {
                uint32_t kb[4];
                ldsm_x4(kb, kbase + ((n2*16 + bRowP) * QSTR + 64 + ks*16 + bColP) * 2);
                mma_bf16(sacc[2*n2],   qh[ks], &kb[0]);
                mma_bf16(sacc[2*n2+1], qh[ks], &kb[2]);
            }
        }

        float mx0 = -1e30f, mx1 = -1e30f;
        #pragma unroll
        for (int nf = 0; nf < 8; nf++) {
            mx0 = fmaxf(mx0, fmaxf(sacc[nf][0], sacc[nf][1]));
            mx1 = fmaxf(mx1, fmaxf(sacc[nf][2], sacc[nf][3]));
        }
        mx0 = fmaxf(mx0, __shfl_xor_sync(0xffffffffu, mx0, 1));
        mx0 = fmaxf(mx0, __shfl_xor_sync(0xffffffffu, mx0, 2));
        mx1 = fmaxf(mx1, __shfl_xor_sync(0xffffffffu, mx1, 1));
        mx1 = fmaxf(mx1, __shfl_xor_sync(0xffffffffu, mx1, 2));
        float mn0 = fmaxf(m0, mx0), mn1 = fmaxf(m1, mx1);
        float f0 = ex2((m0 - mn0) * LOG2E), f1 = ex2((m1 - mn1) * LOG2E);

        if (!__all_sync(0xffffffffu, (f0 == 1.f) && (f1 == 1.f))) {
            l0p *= f0; l1p *= f1;
            #pragma unroll
            for (int df = 0; df < 8; df++) {
                oacc[df][0] *= f0; oacc[df][1] *= f0;
                oacc[df][2] *= f1; oacc[df][3] *= f1;
            }
        }
        m0 = mn0; m1 = mn1;

        #pragma unroll
        for (int nf = 0; nf < 8; nf++) {
            sacc[nf][0] = ex2((sacc[nf][0] - mn0) * LOG2E);
            sacc[nf][1] = ex2((sacc[nf][1] - mn0) * LOG2E);
            sacc[nf][2] = ex2((sacc[nf][2] - mn1) * LOG2E);
            sacc[nf][3] = ex2((sacc[nf][3] - mn1) * LOG2E);
            l0p += sacc[nf][0] + sacc[nf][1];
            l1p += sacc[nf][2] + sacc[nf][3];
        }

        uint32_t phi[4][4], plo[4][4];
        #pragma unroll
        for (int ks = 0; ks < 4; ks++) {
            int j = 2 * ks;
            float p00 = sacc[j][0],   p01 = sacc[j][1];
            float p02 = sacc[j][2],   p03 = sacc[j][3];
            float p10 = sacc[j+1][0], p11 = sacc[j+1][1];
            float p12 = sacc[j+1][2], p13 = sacc[j+1][3];
            phi[ks][0] = packbf2(p00, p01);
            phi[ks][1] = packbf2(p02, p03);
            phi[ks][2] = packbf2(p10, p11);
            phi[ks][3] = packbf2(p12, p13);
            __nv_bfloat162* hp;
            hp = (__nv_bfloat162*)&phi[ks][0];
            plo[ks][0] = packbf2(p00 - __bfloat162float(hp->x), p01 - __bfloat162float(hp->y));
            hp = (__nv_bfloat162*)&phi[ks][1];
            plo[ks][1] = packbf2(p02 - __bfloat162float(hp->x), p03 - __bfloat162float(hp->y));
            hp = (__nv_bfloat162*)&phi[ks][2];
            plo[ks][2] = packbf2(p10 - __bfloat162float(hp->x), p11 - __bfloat162float(hp->y));
            hp = (__nv_bfloat162*)&phi[ks][3];
            plo[ks][3] = packbf2(p12 - __bfloat162float(hp->x), p13 - __bfloat162float(hp->y));
        }

        #pragma unroll
        for (int d2 = 0; d2 < 4; d2++) {
            #pragma unroll
            for (int ks = 0; ks < 4; ks++) {
                uint32_t vb[4];
                ldsm_x4(vb, vbase + ((d2*16 + bRowP) * QSTR + ks*16 + bColP) * 2);
                mma_bf16(oacc[2*d2],   phi[ks], &vb[0]);
                mma_bf16(oacc[2*d2+1], phi[ks], &vb[2]);
                mma_bf16(oacc[2*d2],   plo[ks], &vb[0]);
                mma_bf16(oacc[2*d2+1], plo[ks], &vb[2]);
            }
            #pragma unroll
            for (int ks = 0; ks < 4; ks++) {
                uint32_t vb[4];
                ldsm_x4(vb, vbase + ((d2*16 + bRowP) * QSTR + 64 + ks*16 + bColP) * 2);
                mma_bf16(oacc[2*d2],   phi[ks], &vb[0]);
                mma_bf16(oacc[2*d2+1], phi[ks], &vb[2]);
            }
        }
    }

    l0p += __shfl_xor_sync(0xffffffffu, l0p, 1);
    l0p += __shfl_xor_sync(0xffffffffu, l0p, 2);
    l1p += __shfl_xor_sync(0xffffffffu, l1p, 1);
    l1p += __shfl_xor_sync(0xffffffffu, l1p, 2);

    float inv0 = 1.f / l0p, inv1 = 1.f / l1p;
    int b = bh >> 3, h = bh & 7;
    int row0 = q0 + w * 16 + (lane >> 2);
    #pragma unroll
    for (int df = 0; df < 8; df++) {
        int chn = h * HD + df * 8 + (lane & 3) * 2;
        #pragma unroll
        for (int r = 0; r < 2; r++) {
            int row = row0 + r * 8;
            float v0 = oacc[df][r*2 + 0] * (r ? inv1 : inv0);
            float v1 = oacc[df][r*2 + 1] * (r ? inv1 : inv0);
            uint32_t hp = packbf2(v0, v1);
            __nv_bfloat162 hb = *(__nv_bfloat162*)&hp;
            uint32_t lp = packbf2(v0 - __bfloat162float(hb.x), v1 - __bfloat162float(hb.y));
            size_t eb = ((size_t)b * N_ + row) * 1024 + chn;
            *(uint32_t*)&g_obuf[eb]       = hp;
            *(uint32_t*)&g_obuf[eb + 512] = lp;
        }
    }
}

// ---------------------------------------------------------------------------
// 4) Proj GEMM + bias + residual -> out[b][c][n]
// ---------------------------------------------------------------------------
__global__ __launch_bounds__(256, 2) void proj_gemm(const float* __restrict__ bias,
                                                    const float* __restrict__ x,
                                                    float* __restrict__ out) {
    int n0 = blockIdx.x * 128, m0 = blockIdx.y * 128, b = blockIdx.z;

    float acc[4][4][4];
    #pragma unroll
    for (int i = 0; i < 4; i++)
        #pragma unroll
        for (int j = 0; j < 4; j++)
            { acc[i][j][0]=0.f; acc[i][j][1]=0.f; acc[i][j][2]=0.f; acc[i][j][3]=0.f; }

    gemm_mainloop(acc,
        g_wproj + (size_t)m0 * 1024,
        g_obuf + ((size_t)b * N_ + n0) * 1024);

    int wid = threadIdx.x >> 5, lane = threadIdx.x & 31;
    int wm = (wid >> 2) * 64, wn = (wid & 3) * 32;

    #pragma unroll
    for (int mi = 0; mi < 4; mi++) {
        #pragma unroll
        for (int half = 0; half < 2; half++) {
            int chn = m0 + wm + mi*16 + (lane >> 2) + half*8;
            float bv = bias[chn];
            size_t rowbase = ((size_t)b * C_ + chn) * N_;
            #pragma unroll
            for (int ni = 0; ni < 4; ni++) {
                int n = n0 + wn + ni*8 + (lane & 3)*2;
                float2 xv = *(const float2*)&x[rowbase + n];
                float2 v;
                v.x = acc[mi][ni][half*2 + 0] + bv + xv.x;
                v.y = acc[mi][ni][half*2 + 1] + bv + xv.y;
                *(float2*)&out[rowbase + n] = v;
            }
        }
    }
}

// ---------------------------------------------------------------------------
extern "C" void kernel_launch(void* const* d_in, const int* in_sizes, int n_in,
                              void* d_out, int out_size) {
    const float* x      = (const float*)d_in[0];
    const float* norm_w = (const float*)d_in[1];
    const float* norm_b = (const float*)d_in[2];
    const float* qkv_w  = (const float*)d_in[3];
    const float* qkv_b  = (const float*)d_in[4];
    const float* proj_w = (const float*)d_in[5];
    const float* proj_b = (const float*)d_in[6];
    float* out = (float*)d_out;

    cudaFuncSetAttribute(qkv_gemm, cudaFuncAttributeMaxDynamicSharedMemorySize, GEMM_SMEM);
    cudaFuncSetAttribute(proj_gemm, cudaFuncAttributeMaxDynamicSharedMemorySize, GEMM_SMEM);
    cudaFuncSetAttribute(attn_kernel, cudaFuncAttributeMaxDynamicSharedMemorySize, ATTN_SMEM);

    convw_kernel<<<4 * C_, 128>>>(qkv_w, proj_w);
    gn_kernel<<<B_ * G_, 256>>>(x, norm_w, norm_b);
    qkv_gemm<<<dim3(N_ / 128, (3 * C_) / 128, B_), 256, GEMM_SMEM>>>(qkv_b);
    attn_kernel<<<dim3(N_ / 128, B_ * NH), 256, ATTN_SMEM>>>();
    proj_gemm<<<dim3(N_ / 128, C_ / 128, B_), 256, GEMM_SMEM>>>(proj_b, x, out);
}